// round 5
// baseline (speedup 1.0000x reference)
#include <cuda_runtime.h>
#include <math.h>

#define Bc 32
#define Tc 64
#define Hc 1024
#define Ec 512
#define Mc 512
#define Vc 32000

// P4 layout: arr[(k>>2)*128 + b*4 + (k&3)]  (k = feature, b = batch lane 0..31)
__device__ float g_siT[Hc*32];
__device__ float g_hidT[Hc*32];
__device__ float g_encT[Bc*Tc*2*Hc];        // enc_out P4, 64 row-groups
__device__ float g_Ua[Bc*Tc*Hc];            // row-major [bt][a]
__device__ float g_e[Bc*Tc];
__device__ float g_xsT[(2*Hc+Ec+Hc)*32];    // P4: [emb(512)|ctx(2048)|si(1024)]
__device__ float g_moinT[(3*Hc+Ec)*32];     // P4: [si(1024)|ctx(2048)|emb(512)]
__device__ float g_mT[Mc*32];
__device__ float g_partA[8*3*Hc*32];        // split-K partials

typedef unsigned long long ull;
typedef unsigned int uint;

__device__ __forceinline__ ull pk2(float x, float y){
    ull r; asm("mov.b64 %0, {%1, %2};" : "=l"(r) : "f"(x), "f"(y)); return r;
}
__device__ __forceinline__ float2 upk2(ull p){
    float2 f; asm("mov.b64 {%0, %1}, %2;" : "=f"(f.x), "=f"(f.y) : "l"(p)); return f;
}
__device__ __forceinline__ void fma2(ull &d, ull a, ull b){
    asm("fma.rn.f32x2 %0, %1, %2, %0;" : "+l"(d) : "l"(a), "l"(b));
}
__device__ __forceinline__ float tanha(float x){
    float y; asm("tanh.approx.f32 %0, %1;" : "=f"(y) : "f"(x)); return y;
}
__device__ __forceinline__ void cpa16(uint s, const void* g){
    asm volatile("cp.async.cg.shared.global [%0], [%1], 16;" :: "r"(s), "l"(g));
}

// ---------------- row-major [rows][K] -> P4 ------------------------------------
__global__ void to_p4(const float* __restrict__ in, float* __restrict__ out, int K){
    int g = blockIdx.y;
    int n4 = (K >> 2) * 32;
    for (int idx = blockIdx.x*blockDim.x + threadIdx.x; idx < n4; idx += gridDim.x*blockDim.x){
        int lane = idx & 31, k4 = idx >> 5;
        float4 v = *(const float4*)(in + (size_t)(g*32 + lane)*K + k4*4);
        *(float4*)(out + (size_t)g*K*32 + k4*128 + lane*4) = v;
    }
}

// ---------------- smem-staged GEMM: 128-col tiles, BK=32, cp.async x2 ---------
// MODE 0: P4 store (+dup to out2 pre-offset). MODE 1: row-major via smem
// transpose (ldo). MODE 3: split-K partial out[(z*N+col)*32+lane].
// MIXED: K axis = [w_ih K=2560 | w_hh K=1024], 6-way split (z<4 ih, z>=4 hh).
template<int KTOT, int SPLITK, int MODE, int MIXED>
__global__ __launch_bounds__(256) void gemmT(
        const float* __restrict__ A, const float* __restrict__ W1,
        const float* __restrict__ W2, const float* __restrict__ bias,
        float* __restrict__ out, float* __restrict__ out2, int ldo, int act)
{
    __shared__ float ws[2][128][32];
    const int tid  = threadIdx.x;
    const int lane = tid & 31;
    const int warp = tid >> 5;
    const int colBase = blockIdx.x * 128;
    constexpr int NT = KTOT / 32;
    int TZ, t0;
    if (SPLITK == 1){ TZ = NT; t0 = 0; }
    else if (!MIXED){ TZ = NT / SPLITK; t0 = blockIdx.z * TZ; }
    else { if (blockIdx.z < 4){ TZ = 20; t0 = blockIdx.z*20; }
           else               { TZ = 16; t0 = 80 + (blockIdx.z-4)*16; } }

    ull acc[16];
#pragma unroll
    for (int v = 0; v < 16; v++) acc[v] = 0ull;

    const float* aP = A + (size_t)blockIdx.y*KTOT*32 + lane*4;

    // prefetch tile t0 -> buf 0
#pragma unroll
    for (int i = 0; i < 4; i++){
        int f = tid + i*256;
        int c = f >> 3, kf = f & 7;
        int kg = t0*32 + kf*4;
        const float* src;
        if (MIXED){
            if (kg >= 2560) src = W2 + (size_t)(colBase + c)*1024 + (kg - 2560);
            else            src = W1 + (size_t)(colBase + c)*2560 + kg;
        } else          src = W1 + (size_t)(colBase + c)*KTOT + kg;
        cpa16((uint)__cvta_generic_to_shared(&ws[0][c][kf*4]), src);
    }
    asm volatile("cp.async.commit_group;");

    for (int t = 0; t < TZ; t++){
        if (t + 1 < TZ){
#pragma unroll
            for (int i = 0; i < 4; i++){
                int f = tid + i*256;
                int c = f >> 3, kf = f & 7;
                int kg = (t0 + t + 1)*32 + kf*4;
                const float* src;
                if (MIXED){
                    if (kg >= 2560) src = W2 + (size_t)(colBase + c)*1024 + (kg - 2560);
                    else            src = W1 + (size_t)(colBase + c)*2560 + kg;
                } else          src = W1 + (size_t)(colBase + c)*KTOT + kg;
                cpa16((uint)__cvta_generic_to_shared(&ws[(t+1)&1][c][kf*4]), src);
            }
            asm volatile("cp.async.commit_group;");
            asm volatile("cp.async.wait_group 1;");
        } else {
            asm volatile("cp.async.wait_group 0;");
        }
        __syncthreads();
        const float* aT = aP + (size_t)(t0 + t)*8*128;
        const float (*wb)[32] = ws[t & 1];
#pragma unroll
        for (int k4 = 0; k4 < 8; k4++){
            float4 a4 = *(const float4*)(aT + k4*128);
            ull a01 = pk2(a4.x, a4.y);
            ull a23 = pk2(a4.z, a4.w);
#pragma unroll
            for (int v = 0; v < 16; v++){
                float4 w4 = *(const float4*)(&wb[warp*16 + v][k4*4]);
                fma2(acc[v], pk2(w4.x, w4.y), a01);
                fma2(acc[v], pk2(w4.z, w4.w), a23);
            }
        }
        __syncthreads();
    }

    const int col0 = colBase + warp*16;

    if (MODE == 3){
        const int N = gridDim.x * 128;
        float* p = out + ((size_t)blockIdx.z*N + col0)*32 + lane;
#pragma unroll
        for (int v = 0; v < 16; v++){
            float2 f = upk2(acc[v]);
            p[v*32] = f.x + f.y;
        }
        return;
    }

    float res[16];
#pragma unroll
    for (int v = 0; v < 16; v++){
        float2 f = upk2(acc[v]);
        res[v] = f.x + f.y + (bias ? bias[col0 + v] : 0.f);
        if (act) res[v] = tanhf(res[v]);
    }

    if (MODE == 0){
        size_t idx = (size_t)(col0 >> 2)*128 + lane*4;
#pragma unroll
        for (int q = 0; q < 4; q++){
            float4 o = make_float4(res[q*4], res[q*4+1], res[q*4+2], res[q*4+3]);
            *(float4*)(out + idx + q*128) = o;
            if (out2) *(float4*)(out2 + idx + q*128) = o;
        }
    } else { // MODE 1: transpose via smem, coalesced row-major store
        float* st = (float*)ws;
#pragma unroll
        for (int v = 0; v < 16; v++)
            st[(warp*16 + v)*33 + lane] = res[v];
        __syncthreads();
        int row = tid >> 3;
        int cg  = (tid & 7) * 16;
        size_t ob = (size_t)(blockIdx.y*32 + row)*ldo + colBase + cg;
#pragma unroll
        for (int q = 0; q < 4; q++)
            *(float4*)(out + ob + q*4) = make_float4(
                st[(cg+q*4+0)*33 + row], st[(cg+q*4+1)*33 + row],
                st[(cg+q*4+2)*33 + row], st[(cg+q*4+3)*33 + row]);
    }
}

// ---------------- fused per-step attention: sWa + yi_emb + energies ----------
__global__ __launch_bounds__(256) void attn_fused(
        const float* __restrict__ Wa, const float* __restrict__ emb_w,
        const float* __restrict__ emb_b, const float* __restrict__ va, int t0flag)
{
    int b = blockIdx.x;
    __shared__ float ssi[Hc], sW[Hc], sva[Hc];
    int tid = threadIdx.x, lane = tid & 31, warp = tid >> 5;

    for (int k = tid; k < Hc; k += 256){
        ssi[k] = g_siT[(size_t)(k>>2)*128 + b*4 + (k&3)];
        sva[k] = va[k];
    }
    __syncthreads();

    // sWa[a] = si[b,:]·Wa[a,:]   (warp handles 128 a's)
    for (int a = warp*128; a < warp*128 + 128; a++){
        const float4* wr = (const float4*)(Wa + (size_t)a*Hc);
        ull acc = 0ull;
#pragma unroll
        for (int j = 0; j < 8; j++){
            int q = j*32 + lane;
            float4 w4 = wr[q];
            float4 s4 = *(const float4*)&ssi[q*4];
            fma2(acc, pk2(w4.x, w4.y), pk2(s4.x, s4.y));
            fma2(acc, pk2(w4.z, w4.w), pk2(s4.z, s4.w));
        }
        float2 f = upk2(acc); float p = f.x + f.y;
#pragma unroll
        for (int o = 16; o > 0; o >>= 1) p += __shfl_xor_sync(0xffffffffu, p, o);
        if (lane == 0) sW[a] = p;
    }

    // yi_emb[c] = yi[b,:]·emb_w[c,:] + emb_b[c]  (yi = si; zero at t=0)
    for (int c = warp*64; c < warp*64 + 64; c++){
        float val;
        if (t0flag){
            val = emb_b[c];
        } else {
            const float4* wr = (const float4*)(emb_w + (size_t)c*Hc);
            ull acc = 0ull;
#pragma unroll
            for (int j = 0; j < 8; j++){
                int q = j*32 + lane;
                float4 w4 = wr[q];
                float4 s4 = *(const float4*)&ssi[q*4];
                fma2(acc, pk2(w4.x, w4.y), pk2(s4.x, s4.y));
                fma2(acc, pk2(w4.z, w4.w), pk2(s4.z, s4.w));
            }
            float2 f = upk2(acc); float p = f.x + f.y;
#pragma unroll
            for (int o = 16; o > 0; o >>= 1) p += __shfl_xor_sync(0xffffffffu, p, o);
            val = p + emb_b[c];
        }
        if (lane == 0){
            g_xsT[(size_t)(c>>2)*128 + b*4 + (c&3)] = val;
            int k = 3*Hc + c;
            g_moinT[(size_t)(k>>2)*128 + b*4 + (k&3)] = val;
        }
    }
    __syncthreads();

    // e[b,t] = sum_a va[a]*tanh(sW[a] + Ua[bt,a])   (warp handles 8 t's)
    for (int tt = warp*8; tt < warp*8 + 8; tt++){
        const float4* ur = (const float4*)(g_Ua + (size_t)(b*Tc + tt)*Hc);
        float p = 0.f;
#pragma unroll
        for (int j = 0; j < 8; j++){
            int q = j*32 + lane;
            float4 u = ur[q];
            float4 s = *(const float4*)&sW[q*4];
            float4 v = *(const float4*)&sva[q*4];
            p += v.x*tanha(s.x+u.x) + v.y*tanha(s.y+u.y)
               + v.z*tanha(s.z+u.z) + v.w*tanha(s.w+u.w);
        }
#pragma unroll
        for (int o = 16; o > 0; o >>= 1) p += __shfl_xor_sync(0xffffffffu, p, o);
        if (lane == 0) g_e[b*Tc + tt] = p;
    }
}

// ---------------- softmax + context ------------------------------------------
__global__ void attn_ctx_kernel(const float* __restrict__ enc_out,
                                float* __restrict__ alphas, int tstep){
    int b = blockIdx.x;
    __shared__ float sal[Tc];
    __shared__ float sinv;
    if (threadIdx.x == 0){
        float mx = -1e30f;
        for (int t = 0; t < Tc; t++) mx = fmaxf(mx, g_e[b*Tc + t]);
        float s = 0.f;
        for (int t = 0; t < Tc; t++){ float ev = __expf(g_e[b*Tc + t] - mx); sal[t] = ev; s += ev; }
        sinv = 1.f / s;
    }
    __syncthreads();
    if (threadIdx.x < Tc) sal[threadIdx.x] *= sinv;
    __syncthreads();
    if (threadIdx.x < Tc)
        alphas[((size_t)b*Tc + tstep)*Tc + threadIdx.x] = sal[threadIdx.x];

    const float4* eo = (const float4*)(enc_out + (size_t)b*Tc*2*Hc);
    for (int f4 = threadIdx.x; f4 < (2*Hc)/4; f4 += blockDim.x){
        float4 acc = make_float4(0.f, 0.f, 0.f, 0.f);
        for (int t = 0; t < Tc; t++){
            float al = sal[t];
            float4 ev = eo[(size_t)t*(2*Hc/4) + f4];
            acc.x += al*ev.x; acc.y += al*ev.y; acc.z += al*ev.z; acc.w += al*ev.w;
        }
        *(float4*)&g_xsT[(size_t)(Ec/4 + f4)*128 + b*4]   = acc;  // k = E + 4f4
        *(float4*)&g_moinT[(size_t)(Hc/4 + f4)*128 + b*4] = acc;  // k = H + 4f4
    }
}

// ---------------- fused split-K reduce + GRU gates ----------------------------
// partials: z 0..3 = gx (w_ih range), z 4..5 = gh (w_hh range); N = 3072
__global__ void gru_fused(const float* __restrict__ b_ih, const float* __restrict__ b_hh){
    int j = blockIdx.x*256 + threadIdx.x;
    if (j >= Hc*32) return;
    int lane = j & 31, col = j >> 5;
    float xr = 0.f, xz = 0.f, xn = 0.f, hr = 0.f, hz = 0.f, hn = 0.f;
#pragma unroll
    for (int z = 0; z < 4; z++){
        size_t ba = (size_t)z*3*Hc*32;
        xr += g_partA[ba + (size_t)(col)*32        + lane];
        xz += g_partA[ba + (size_t)(Hc + col)*32   + lane];
        xn += g_partA[ba + (size_t)(2*Hc + col)*32 + lane];
    }
#pragma unroll
    for (int z = 4; z < 6; z++){
        size_t ba = (size_t)z*3*Hc*32;
        hr += g_partA[ba + (size_t)(col)*32        + lane];
        hz += g_partA[ba + (size_t)(Hc + col)*32   + lane];
        hn += g_partA[ba + (size_t)(2*Hc + col)*32 + lane];
    }
    xr += b_ih[col];        hr += b_hh[col];
    xz += b_ih[Hc + col];   hz += b_hh[Hc + col];
    xn += b_ih[2*Hc + col]; hn += b_hh[2*Hc + col];
    float r = 1.f/(1.f + __expf(-(xr + hr)));
    float z = 1.f/(1.f + __expf(-(xz + hz)));
    float n = tanhf(xn + r*hn);
    size_t p4 = (size_t)(col >> 2)*128 + lane*4 + (col & 3);
    float s  = g_siT[p4];
    float sn = (1.f - z)*n + z*s;
    g_siT[p4]   = sn;
    g_moinT[p4] = sn;
    g_xsT[(size_t)(640 + (col >> 2))*128 + lane*4 + (col & 3)] = sn;  // k = 2560+col
}

// ---------------- fused split-K reduce + maxout -------------------------------
__global__ void mo_reduce(const float* __restrict__ mo_b){
    int j = blockIdx.x*256 + threadIdx.x;
    if (j >= Mc*32) return;
    int lane = j & 31, m = j >> 5;
    float s0 = 0.f, s1 = 0.f;
#pragma unroll
    for (int z = 0; z < 8; z++){
        size_t ba = (size_t)z*2*Mc*32;
        s0 += g_partA[ba + (size_t)(2*m)*32   + lane];
        s1 += g_partA[ba + (size_t)(2*m+1)*32 + lane];
    }
    float val = fmaxf(s0 + mo_b[2*m], s1 + mo_b[2*m + 1]);
    g_mT[(size_t)(m >> 2)*128 + lane*4 + (m & 3)] = val;
}

// ---------------- launch ------------------------------------------------------
extern "C" void kernel_launch(void* const* d_in, const int* in_sizes, int n_in,
                              void* d_out, int out_size)
{
    const float* enc_out = (const float*)d_in[0];
    const float* hidden  = (const float*)d_in[1];
    const float* Ws_w    = (const float*)d_in[2];
    const float* Ws_b    = (const float*)d_in[3];
    const float* emb_w   = (const float*)d_in[4];
    const float* emb_b   = (const float*)d_in[5];
    const float* w_ih    = (const float*)d_in[6];
    const float* w_hh    = (const float*)d_in[7];
    const float* b_ih    = (const float*)d_in[8];
    const float* b_hh    = (const float*)d_in[9];
    const float* Wa      = (const float*)d_in[10];
    const float* Ua      = (const float*)d_in[11];
    const float* va      = (const float*)d_in[12];
    const float* mo_w    = (const float*)d_in[13];
    const float* mo_b    = (const float*)d_in[14];
    const float* fc_w    = (const float*)d_in[15];
    const float* fc_b    = (const float*)d_in[16];

    float* logits = (float*)d_out;                       // [B,T,V]
    float* alphas = logits + (size_t)Bc*Tc*Vc;           // [B,T,T]

    float *psiT, *phidT, *pencT, *pUa, *pxsT, *pmoinT, *pmT, *ppA;
    cudaGetSymbolAddress((void**)&psiT,   g_siT);
    cudaGetSymbolAddress((void**)&phidT,  g_hidT);
    cudaGetSymbolAddress((void**)&pencT,  g_encT);
    cudaGetSymbolAddress((void**)&pUa,    g_Ua);
    cudaGetSymbolAddress((void**)&pxsT,   g_xsT);
    cudaGetSymbolAddress((void**)&pmoinT, g_moinT);
    cudaGetSymbolAddress((void**)&pmT,    g_mT);
    cudaGetSymbolAddress((void**)&ppA,    g_partA);

    // ---- one-time setup
    to_p4<<<dim3(4, 1), 256>>>(hidden + Bc*Hc, phidT, Hc);
    to_p4<<<dim3(8, (Bc*Tc)/32), 256>>>(enc_out, pencT, 2*Hc);
    // si0 = tanh(hidden1 @ Ws_w^T + Ws_b) -> siT (+ dup into xsT si slot)
    gemmT<Hc,1,0,0><<<dim3(Hc/128, 1), 256>>>(phidT, Ws_w, nullptr, Ws_b,
                                              psiT, pxsT + (size_t)640*128, 0, 1);
    // Ua_enc = enc_out @ Ua^T -> row-major [bt][a]
    gemmT<2*Hc,1,1,0><<<dim3(Hc/128, (Bc*Tc)/32), 256>>>(pencT, Ua, nullptr, nullptr,
                                                         pUa, nullptr, Hc, 0);

    for (int t = 0; t < Tc; t++){
        attn_fused<<<Bc, 256>>>(Wa, emb_w, emb_b, va, t == 0 ? 1 : 0);
        attn_ctx_kernel<<<Bc, 256>>>(enc_out, alphas, t);
        // gates partial: [emb|ctx|si] @ [w_ih|w_hh]^T, 6-way mixed split-K
        gemmT<3*Hc+Ec,6,3,1><<<dim3(3*Hc/128, 1, 6), 256>>>(pxsT, w_ih, w_hh, nullptr,
                                                            ppA, nullptr, 0, 0);
        gru_fused<<<(Hc*32 + 255)/256, 256>>>(b_ih, b_hh);
        // maxout partials (split-K 8) + fused reduce/maxout
        gemmT<3*Hc+Ec,8,3,0><<<dim3(2*Mc/128, 1, 8), 256>>>(pmoinT, mo_w, nullptr, nullptr,
                                                            ppA, nullptr, 0, 0);
        mo_reduce<<<(Mc*32 + 255)/256, 256>>>(mo_b);
        // logits[:, t, :] = m @ fc_w^T + fc_b
        gemmT<Mc,1,1,0><<<dim3(Vc/128, 1), 256>>>(pmT, fc_w, nullptr, fc_b,
                                                  logits + (size_t)t*Vc, nullptr, Tc*Vc, 0);
    }
}

// round 7
// speedup vs baseline: 2.4441x; 2.4441x over previous
#include <cuda_runtime.h>
#include <cuda_bf16.h>
#include <math.h>

#define Bc 32
#define Tc 64
#define Hc 1024
#define Ec 512
#define Mc 512
#define Vc 32000

typedef unsigned int uint;
typedef unsigned long long ull;

// ---------------- f32 scratch (device globals) --------------------------------
__device__ __align__(256) float g_sWa[Bc*Hc];          // [b][a]
__device__ __align__(256) float g_Ua[Bc*Tc*Hc];        // [bt][a]
__device__ __align__(256) float g_xs[Bc*3584];         // [b][ emb 0:512 | ctx 512:2560 | si 2560:3584 ]
__device__ __align__(256) float g_moin[Bc*3584];       // [b][ si 0:1024 | ctx 1024:3072 | emb 3072:3584 ]
__device__ __align__(256) float g_m[Bc*Mc];            // [b][m]
__device__ __align__(256) float g_part[6*3072*32];     // split-K partials [(z*N+col)*32+b]

// ---------------- bf16 hi/lo weight copies (converted once) -------------------
__device__ __align__(256) __nv_bfloat16 s_fc_hi[Vc*Mc],        s_fc_lo[Vc*Mc];
__device__ __align__(256) __nv_bfloat16 s_ih_hi[3*Hc*2560],    s_ih_lo[3*Hc*2560];
__device__ __align__(256) __nv_bfloat16 s_hh_hi[3*Hc*Hc],      s_hh_lo[3*Hc*Hc];
__device__ __align__(256) __nv_bfloat16 s_mo_hi[2*Mc*3584],    s_mo_lo[2*Mc*3584];
__device__ __align__(256) __nv_bfloat16 s_ua_hi[Hc*2*Hc],      s_ua_lo[Hc*2*Hc];
__device__ __align__(256) __nv_bfloat16 s_cat_hi[1536*Hc],     s_cat_lo[1536*Hc];  // [Wa | emb]
__device__ __align__(256) __nv_bfloat16 s_ws_hi[Hc*Hc],        s_ws_lo[Hc*Hc];

// ---------------- PTX helpers --------------------------------------------------
__device__ __forceinline__ uint smem_u32(const void* p){
    uint a; asm("{ .reg .u64 t; cvta.to.shared.u64 t, %1; cvt.u32.u64 %0, t; }" : "=r"(a) : "l"(p));
    return a;
}
__device__ __forceinline__ float tanha(float x){
    float y; asm("tanh.approx.f32 %0, %1;" : "=f"(y) : "f"(x)); return y;
}
__device__ __forceinline__ void cpa16(uint s, const void* g){
    asm volatile("cp.async.cg.shared.global [%0], [%1], 16;" :: "r"(s), "l"(g));
}
__device__ __forceinline__ void ldm4(uint addr, uint &r0, uint &r1, uint &r2, uint &r3){
    asm volatile("ldmatrix.sync.aligned.m8n8.x4.shared.b16 {%0,%1,%2,%3}, [%4];"
        : "=r"(r0), "=r"(r1), "=r"(r2), "=r"(r3) : "r"(addr));
}
__device__ __forceinline__ void mma16816(float* c, uint a0, uint a1, uint a2, uint a3,
                                         uint b0, uint b1){
    asm volatile("mma.sync.aligned.m16n8k16.row.col.f32.bf16.bf16.f32 "
        "{%0,%1,%2,%3}, {%4,%5,%6,%7}, {%8,%9}, {%0,%1,%2,%3};"
        : "+f"(c[0]), "+f"(c[1]), "+f"(c[2]), "+f"(c[3])
        : "r"(a0), "r"(a1), "r"(a2), "r"(a3), "r"(b0), "r"(b1));
}

// ---------------- smem layout (bf16 elems, padded row stride 72) --------------
// A tile: 128 x 64 (stride 72)  = 9216 elems = 18432 B per matrix
// B tile:  32 x 64 (stride 72)  = 2304 elems =  4608 B per matrix
#define APITCH 72
#define A_ELE (128*APITCH)
#define B_ELE (32*APITCH)
#define SM_AHI 0
#define SM_ALO (SM_AHI + 2*A_ELE)          // [buf][...]
#define SM_BHI (SM_ALO + 2*A_ELE)
#define SM_BLO (SM_BHI + 2*B_ELE)
#define SM_ELE (SM_BLO + 2*B_ELE)          // total bf16 elems
#define SM_DYN (SM_ELE*2)                   // bytes = 92160

// ---------------- weight f32 -> bf16 hi/lo ------------------------------------
__global__ void conv_hl(const float* __restrict__ src, __nv_bfloat16* __restrict__ hi,
                        __nv_bfloat16* __restrict__ lo, int n){
    for (int i = blockIdx.x*256 + threadIdx.x; i < n; i += gridDim.x*256){
        float x = src[i];
        __nv_bfloat16 h = __float2bfloat16(x);
        hi[i] = h;
        lo[i] = __float2bfloat16(x - __bfloat162float(h));
    }
}

// ---------------- HMMA GEMM: out[32, Ncols] = act(B @ A^T + bias) -------------
// A (weights) row-major [col][K] bf16 hi/lo; B (activations) f32 [row][Bstride].
// Block: M=128 cols (warp*16), N=32 batch; K chunks of 64, cp.async dbl-buffer.
// MODE 0: row-major out[(rowBase+n)*ldo + col] (+bias, opt tanh)
// MODE 1: partial dump g_part[((zbase+z)*Ncols + col)*32 + n]
// MODE 2: PRE: col<1024 -> g_sWa ; col>=1024 -> +emb_b into g_xs & g_moin
template<int MODE>
__global__ void __launch_bounds__(256) hm_gemm(
        const __nv_bfloat16* __restrict__ Ahi, const __nv_bfloat16* __restrict__ Alo,
        int Astride, int chunksPerZ,
        const float* __restrict__ Bsrc, int Bstride, int BkBase,
        const float* __restrict__ bias, float* __restrict__ out, long ldo,
        int Ncols, int zbase, int act, int t0flag)
{
    extern __shared__ __nv_bfloat16 smem[];
    const int tid  = threadIdx.x;
    const int lane = tid & 31;
    const int warp = tid >> 5;
    const int bz   = blockIdx.z;
    const int colBase = blockIdx.x * 128;
    const int rowBase = blockIdx.y * 32;

    if (MODE == 2 && t0flag && colBase >= 1024){
        // yi = 0 at t=0: emb output is just the bias
        for (int i = tid; i < 128*32; i += 256){
            int c2 = colBase - 1024 + (i >> 5);
            int b  = i & 31;
            float v = bias[c2];
            g_xs[b*3584 + c2] = v;
            g_moin[b*3584 + 3072 + c2] = v;
        }
        return;
    }

    const int NC    = chunksPerZ;
    const int Akoff = bz * chunksPerZ * 64;
    const int Bkoff = BkBase + bz * chunksPerZ * 64;
    const uint sb   = smem_u32(smem);

    float acc[4][4];
#pragma unroll
    for (int nt = 0; nt < 4; nt++)
#pragma unroll
        for (int q = 0; q < 4; q++) acc[nt][q] = 0.f;

    // ---- prefetch A chunk c into buffer bi (8x cp.async 16B per thread)
    auto prefA = [&](int c, int bi){
#pragma unroll
        for (int i = 0; i < 4; i++){
            int f  = tid + i*256;
            int r  = f >> 3, kc = f & 7;
            size_t so = (size_t)(colBase + r)*Astride + Akoff + c*64 + kc*8;
            uint dst = (uint)((r*APITCH + kc*8)*2);
            cpa16(sb + (SM_AHI + bi*A_ELE)*2 + dst, Ahi + so);
            cpa16(sb + (SM_ALO + bi*A_ELE)*2 + dst, Alo + so);
        }
        asm volatile("cp.async.commit_group;");
    };
    // ---- convert B chunk c (32x64 f32 -> bf16 hi/lo) into buffer bi
    auto convB = [&](int c, int bi){
        int r  = tid >> 3, k0 = (tid & 7)*8;
        const float* src = Bsrc + (size_t)(rowBase + r)*Bstride + Bkoff + c*64 + k0;
        float4 f0 = *(const float4*)(src);
        float4 f1 = *(const float4*)(src + 4);
        float xs8[8] = {f0.x, f0.y, f0.z, f0.w, f1.x, f1.y, f1.z, f1.w};
        __nv_bfloat16 h8[8], l8[8];
#pragma unroll
        for (int j = 0; j < 8; j++){
            h8[j] = __float2bfloat16(xs8[j]);
            l8[j] = __float2bfloat16(xs8[j] - __bfloat162float(h8[j]));
        }
        *(uint4*)(&smem[SM_BHI + bi*B_ELE + r*APITCH + k0]) = *(uint4*)h8;
        *(uint4*)(&smem[SM_BLO + bi*B_ELE + r*APITCH + k0]) = *(uint4*)l8;
    };

    prefA(0, 0);
    convB(0, 0);

    // per-lane ldmatrix addresses
    const int i8   = lane & 7;
    const int quad = lane >> 3;
    // A: row = w*16 + i8 + (quad&1)*8 ; k = (quad>>1)*8
    const uint aoff = (uint)(((warp*16 + i8 + (quad&1)*8)*APITCH + (quad>>1)*8)*2);
    // B: n = (quad>>1)*8 + i8 ; k = (quad&1)*8   (n-half added later: +16 rows)
    const uint boff = (uint)((((quad>>1)*8 + i8)*APITCH + (quad&1)*8)*2);

    for (int c = 0; c < NC; c++){
        int bi = c & 1;
        if (c + 1 < NC){
            prefA(c + 1, bi ^ 1);
            convB(c + 1, bi ^ 1);
            asm volatile("cp.async.wait_group 1;");
        } else {
            asm volatile("cp.async.wait_group 0;");
        }
        __syncthreads();

        uint aHi = sb + (SM_AHI + bi*A_ELE)*2 + aoff;
        uint aLo = sb + (SM_ALO + bi*A_ELE)*2 + aoff;
        uint bHi = sb + (SM_BHI + bi*B_ELE)*2 + boff;
        uint bLo = sb + (SM_BLO + bi*B_ELE)*2 + boff;

#pragma unroll
        for (int ks = 0; ks < 4; ks++){
            uint kd = (uint)(ks*16*2);
            uint ah[4], al[4], bh0[4], bh1[4], bl0[4], bl1[4];
            ldm4(aHi + kd, ah[0], ah[1], ah[2], ah[3]);
            ldm4(aLo + kd, al[0], al[1], al[2], al[3]);
            ldm4(bHi + kd,                bh0[0], bh0[1], bh0[2], bh0[3]);
            ldm4(bHi + kd + 16*APITCH*2,  bh1[0], bh1[1], bh1[2], bh1[3]);
            ldm4(bLo + kd,                bl0[0], bl0[1], bl0[2], bl0[3]);
            ldm4(bLo + kd + 16*APITCH*2,  bl1[0], bl1[1], bl1[2], bl1[3]);
            // nt 0,1 from half 0 ; nt 2,3 from half 1
            mma16816(acc[0], ah[0],ah[1],ah[2],ah[3], bh0[0], bh0[1]);
            mma16816(acc[1], ah[0],ah[1],ah[2],ah[3], bh0[2], bh0[3]);
            mma16816(acc[2], ah[0],ah[1],ah[2],ah[3], bh1[0], bh1[1]);
            mma16816(acc[3], ah[0],ah[1],ah[2],ah[3], bh1[2], bh1[3]);
            mma16816(acc[0], ah[0],ah[1],ah[2],ah[3], bl0[0], bl0[1]);
            mma16816(acc[1], ah[0],ah[1],ah[2],ah[3], bl0[2], bl0[3]);
            mma16816(acc[2], ah[0],ah[1],ah[2],ah[3], bl1[0], bl1[1]);
            mma16816(acc[3], ah[0],ah[1],ah[2],ah[3], bl1[2], bl1[3]);
            mma16816(acc[0], al[0],al[1],al[2],al[3], bh0[0], bh0[1]);
            mma16816(acc[1], al[0],al[1],al[2],al[3], bh0[2], bh0[3]);
            mma16816(acc[2], al[0],al[1],al[2],al[3], bh1[0], bh1[1]);
            mma16816(acc[3], al[0],al[1],al[2],al[3], bh1[2], bh1[3]);
        }
        __syncthreads();
    }

    // ---- epilogue: lane holds rows g,(g+8); cols nt*8 + 2*tig (+1)
    const int g   = lane >> 2;
    const int tig = lane & 3;
#pragma unroll
    for (int nt = 0; nt < 4; nt++){
#pragma unroll
        for (int q = 0; q < 4; q++){
            int colm = colBase + warp*16 + g + ((q >> 1) ? 8 : 0);
            int n    = nt*8 + 2*tig + (q & 1);
            float v  = acc[nt][q];
            if (MODE == 0){
                v += bias ? bias[colm] : 0.f;
                if (act) v = tanhf(v);
                out[(size_t)(rowBase + n)*ldo + colm] = v;
            } else if (MODE == 1){
                g_part[((size_t)(zbase + bz)*Ncols + colm)*32 + n] = v;
            } else {
                if (colm < 1024){
                    g_sWa[n*1024 + colm] = v;
                } else {
                    int c2 = colm - 1024;
                    float o = v + bias[c2];
                    g_xs[n*3584 + c2] = o;
                    g_moin[n*3584 + 3072 + c2] = o;
                }
            }
        }
    }
}

// ---------------- fused attention: energies + softmax + context ---------------
__global__ void __launch_bounds__(256) attn_all(const float* __restrict__ enc_out,
                                                const float* __restrict__ va,
                                                float* __restrict__ alphas, int tstep){
    int b = blockIdx.x;
    __shared__ float sW[Hc], sva[Hc], sal[Tc];
    __shared__ float sinv;
    int tid = threadIdx.x, lane = tid & 31, warp = tid >> 5;

    for (int k = tid; k < Hc; k += 256){
        sW[k]  = g_sWa[b*Hc + k];
        sva[k] = va[k];
    }
    __syncthreads();

    for (int j = 0; j < 8; j++){
        int t = warp*8 + j;
        const float4* ur = (const float4*)(g_Ua + (size_t)(b*Tc + t)*Hc);
        float p = 0.f;
#pragma unroll
        for (int q = 0; q < 8; q++){
            int i = q*32 + lane;
            float4 u = ur[i];
            float4 s = *(const float4*)&sW[i*4];
            float4 v = *(const float4*)&sva[i*4];
            p += v.x*tanha(s.x+u.x) + v.y*tanha(s.y+u.y)
               + v.z*tanha(s.z+u.z) + v.w*tanha(s.w+u.w);
        }
#pragma unroll
        for (int o = 16; o > 0; o >>= 1) p += __shfl_xor_sync(0xffffffffu, p, o);
        if (lane == 0) sal[t] = p;
    }
    __syncthreads();
    if (tid == 0){
        float mx = -1e30f;
        for (int t = 0; t < Tc; t++) mx = fmaxf(mx, sal[t]);
        float s = 0.f;
        for (int t = 0; t < Tc; t++){ float ev = __expf(sal[t] - mx); sal[t] = ev; s += ev; }
        sinv = 1.f / s;
    }
    __syncthreads();
    if (tid < Tc) sal[tid] *= sinv;
    __syncthreads();
    if (tid < Tc)
        alphas[((size_t)b*Tc + tstep)*Tc + tid] = sal[tid];

    const float4* eo = (const float4*)(enc_out + (size_t)b*Tc*2*Hc);
    for (int f4 = tid; f4 < (2*Hc)/4; f4 += 256){
        float4 acc = make_float4(0.f, 0.f, 0.f, 0.f);
        for (int t = 0; t < Tc; t++){
            float al = sal[t];
            float4 ev = eo[(size_t)t*(2*Hc/4) + f4];
            acc.x += al*ev.x; acc.y += al*ev.y; acc.z += al*ev.z; acc.w += al*ev.w;
        }
        int f = f4*4;
        *(float4*)&g_xs[b*3584 + Ec + f]   = acc;
        *(float4*)&g_moin[b*3584 + Hc + f] = acc;
    }
}

// ---------------- fused split-K reduce + GRU gates ----------------------------
__global__ void gru_fused(const float* __restrict__ b_ih, const float* __restrict__ b_hh){
    int j = blockIdx.x*256 + threadIdx.x;
    if (j >= Hc*32) return;
    int b = j & 31, col = j >> 5;
    float xr = 0.f, xz = 0.f, xn = 0.f, hr = 0.f, hz = 0.f, hn = 0.f;
#pragma unroll
    for (int z = 0; z < 4; z++){
        size_t ba = (size_t)z*3*Hc*32;
        xr += g_part[ba + (size_t)(col)*32        + b];
        xz += g_part[ba + (size_t)(Hc + col)*32   + b];
        xn += g_part[ba + (size_t)(2*Hc + col)*32 + b];
    }
#pragma unroll
    for (int z = 4; z < 6; z++){
        size_t ba = (size_t)z*3*Hc*32;
        hr += g_part[ba + (size_t)(col)*32        + b];
        hz += g_part[ba + (size_t)(Hc + col)*32   + b];
        hn += g_part[ba + (size_t)(2*Hc + col)*32 + b];
    }
    xr += b_ih[col];        hr += b_hh[col];
    xz += b_ih[Hc + col];   hz += b_hh[Hc + col];
    xn += b_ih[2*Hc + col]; hn += b_hh[2*Hc + col];
    float r = 1.f/(1.f + __expf(-(xr + hr)));
    float z = 1.f/(1.f + __expf(-(xz + hz)));
    float n = tanhf(xn + r*hn);
    float s  = g_xs[b*3584 + 2560 + col];
    float sn = (1.f - z)*n + z*s;
    g_xs[b*3584 + 2560 + col] = sn;
    g_moin[b*3584 + col]      = sn;
}

// ---------------- fused split-K reduce + maxout -------------------------------
__global__ void mo_reduce(const float* __restrict__ mo_b){
    int j = blockIdx.x*256 + threadIdx.x;
    if (j >= Mc*32) return;
    int b = j & 31, m = j >> 5;
    float s0 = 0.f, s1 = 0.f;
#pragma unroll
    for (int z = 0; z < 4; z++){
        size_t ba = (size_t)z*2*Mc*32;
        s0 += g_part[ba + (size_t)(2*m)*32   + b];
        s1 += g_part[ba + (size_t)(2*m+1)*32 + b];
    }
    g_m[b*Mc + m] = fmaxf(s0 + mo_b[2*m], s1 + mo_b[2*m + 1]);
}

// ---------------- launch ------------------------------------------------------
extern "C" void kernel_launch(void* const* d_in, const int* in_sizes, int n_in,
                              void* d_out, int out_size)
{
    const float* enc_out = (const float*)d_in[0];
    const float* hidden  = (const float*)d_in[1];
    const float* Ws_w    = (const float*)d_in[2];
    const float* Ws_b    = (const float*)d_in[3];
    const float* emb_w   = (const float*)d_in[4];
    const float* emb_b   = (const float*)d_in[5];
    const float* w_ih    = (const float*)d_in[6];
    const float* w_hh    = (const float*)d_in[7];
    const float* b_ih    = (const float*)d_in[8];
    const float* b_hh    = (const float*)d_in[9];
    const float* Wa      = (const float*)d_in[10];
    const float* Ua      = (const float*)d_in[11];
    const float* va      = (const float*)d_in[12];
    const float* mo_w    = (const float*)d_in[13];
    const float* mo_b    = (const float*)d_in[14];
    const float* fc_w    = (const float*)d_in[15];
    const float* fc_b    = (const float*)d_in[16];

    float* logits = (float*)d_out;
    float* alphas = logits + (size_t)Bc*Tc*Vc;

    float *pxs, *pmoin, *pm, *pUa;
    __nv_bfloat16 *fc_h, *fc_l, *ih_h, *ih_l, *hh_h, *hh_l, *mo_h, *mo_l,
                  *ua_h, *ua_l, *cat_h, *cat_l, *ws_h, *ws_l;
    cudaGetSymbolAddress((void**)&pxs,   g_xs);
    cudaGetSymbolAddress((void**)&pmoin, g_moin);
    cudaGetSymbolAddress((void**)&pm,    g_m);
    cudaGetSymbolAddress((void**)&pUa,   g_Ua);
    cudaGetSymbolAddress((void**)&fc_h,  s_fc_hi);  cudaGetSymbolAddress((void**)&fc_l,  s_fc_lo);
    cudaGetSymbolAddress((void**)&ih_h,  s_ih_hi);  cudaGetSymbolAddress((void**)&ih_l,  s_ih_lo);
    cudaGetSymbolAddress((void**)&hh_h,  s_hh_hi);  cudaGetSymbolAddress((void**)&hh_l,  s_hh_lo);
    cudaGetSymbolAddress((void**)&mo_h,  s_mo_hi);  cudaGetSymbolAddress((void**)&mo_l,  s_mo_lo);
    cudaGetSymbolAddress((void**)&ua_h,  s_ua_hi);  cudaGetSymbolAddress((void**)&ua_l,  s_ua_lo);
    cudaGetSymbolAddress((void**)&cat_h, s_cat_hi); cudaGetSymbolAddress((void**)&cat_l, s_cat_lo);
    cudaGetSymbolAddress((void**)&ws_h,  s_ws_hi);  cudaGetSymbolAddress((void**)&ws_l,  s_ws_lo);

    cudaFuncSetAttribute(hm_gemm<0>, cudaFuncAttributeMaxDynamicSharedMemorySize, SM_DYN);
    cudaFuncSetAttribute(hm_gemm<1>, cudaFuncAttributeMaxDynamicSharedMemorySize, SM_DYN);
    cudaFuncSetAttribute(hm_gemm<2>, cudaFuncAttributeMaxDynamicSharedMemorySize, SM_DYN);

    // ---- one-time weight conversion f32 -> bf16 hi/lo
    conv_hl<<<2048, 256>>>(fc_w,  fc_h,  fc_l,  Vc*Mc);
    conv_hl<<<2048, 256>>>(w_ih,  ih_h,  ih_l,  3*Hc*2560);
    conv_hl<<<1024, 256>>>(w_hh,  hh_h,  hh_l,  3*Hc*Hc);
    conv_hl<<<1024, 256>>>(mo_w,  mo_h,  mo_l,  2*Mc*3584);
    conv_hl<<<1024, 256>>>(Ua,    ua_h,  ua_l,  Hc*2*Hc);
    conv_hl<<<512,  256>>>(Wa,    cat_h, cat_l, Hc*Hc);
    conv_hl<<<512,  256>>>(emb_w, cat_h + (size_t)Hc*Hc, cat_l + (size_t)Hc*Hc, Ec*Hc);
    conv_hl<<<512,  256>>>(Ws_w,  ws_h,  ws_l,  Hc*Hc);

    // ---- si0 = tanh(hidden[1] @ Ws_w^T + Ws_b) -> xs si slot
    hm_gemm<0><<<dim3(8,1,1), 256, SM_DYN>>>(ws_h, ws_l, Hc, 16,
        hidden + Bc*Hc, Hc, 0, Ws_b, pxs + 2560, 3584, 0, 0, 1, 0);
    // ---- Ua_enc = enc_out @ Ua^T -> g_Ua[bt][a]
    hm_gemm<0><<<dim3(8,64,1), 256, SM_DYN>>>(ua_h, ua_l, 2*Hc, 32,
        enc_out, 2*Hc, 0, nullptr, pUa, Hc, 0, 0, 0, 0);

    for (int t = 0; t < Tc; t++){
        // PRE: [Wa | emb] @ si  ->  sWa + emb slots of xs/moin
        hm_gemm<2><<<dim3(12,1,1), 256, SM_DYN>>>(cat_h, cat_l, Hc, 16,
            pxs, 3584, 2560, emb_b, nullptr, 0, 0, 0, 0, t == 0 ? 1 : 0);
        // attention: energies + softmax + context (+alphas)
        attn_all<<<Bc, 256>>>(enc_out, va, alphas, t);
        // gates: gx partials (z 0..3), gh partials (z 4..5)
        hm_gemm<1><<<dim3(24,1,4), 256, SM_DYN>>>(ih_h, ih_l, 2560, 10,
            pxs, 3584, 0, nullptr, nullptr, 0, 3*Hc, 0, 0, 0);
        hm_gemm<1><<<dim3(24,1,2), 256, SM_DYN>>>(hh_h, hh_l, Hc, 8,
            pxs, 3584, 2560, nullptr, nullptr, 0, 3*Hc, 4, 0, 0);
        gru_fused<<<(Hc*32 + 255)/256, 256>>>(b_ih, b_hh);
        // maxout GEMM partials (z 0..3) + fused reduce
        hm_gemm<1><<<dim3(8,1,4), 256, SM_DYN>>>(mo_h, mo_l, 3584, 14,
            pmoin, 3584, 0, nullptr, nullptr, 0, 2*Mc, 0, 0, 0);
        mo_reduce<<<(Mc*32 + 255)/256, 256>>>(mo_b);
        // logits[:, t, :] = m @ fc_w^T + fc_b
        hm_gemm<0><<<dim3(250,1,1), 256, SM_DYN>>>(fc_h, fc_l, Mc, 8,
            pm, Mc, 0, fc_b, logits + (size_t)t*Vc, (long)Tc*Vc, 0, 0, 0, 0);
    }
}

// round 9
// speedup vs baseline: 2.8882x; 1.1817x over previous
#include <cuda_runtime.h>
#include <cuda_bf16.h>
#include <math.h>

#define Bc 32
#define Tc 64
#define Hc 1024
#define Ec 512
#define Mc 512
#define Vc 32000
#define NBLK 146

typedef unsigned int uint;
typedef unsigned long long ull;

// ---------------- f32 scratch --------------------------------------------------
__device__ __align__(256) float g_sWa[Bc*Hc];
__device__ __align__(256) float g_Ua[Bc*Tc*Hc];
__device__ __align__(256) float g_xs[Bc*3584];    // [b][ emb 0:512 | ctx 512:2560 | si 2560:3584 ]
__device__ __align__(256) float g_moin[Bc*3584];  // [b][ si 0:1024 | ctx 1024:3072 | emb 3072:3584 ]
__device__ __align__(256) float g_m[Bc*Mc];
__device__ __align__(256) float g_part[6*3072*32];

__device__ uint g_bar_count;
__device__ uint g_bar_gen;

// ---------------- bf16 hi/lo weights -------------------------------------------
__device__ __align__(256) __nv_bfloat16 s_fc_hi[Vc*Mc],     s_fc_lo[Vc*Mc];
__device__ __align__(256) __nv_bfloat16 s_ih_hi[3*Hc*2560], s_ih_lo[3*Hc*2560];
__device__ __align__(256) __nv_bfloat16 s_hh_hi[3*Hc*Hc],   s_hh_lo[3*Hc*Hc];
__device__ __align__(256) __nv_bfloat16 s_mo_hi[2*Mc*3584], s_mo_lo[2*Mc*3584];
__device__ __align__(256) __nv_bfloat16 s_ua_hi[Hc*2*Hc],   s_ua_lo[Hc*2*Hc];
__device__ __align__(256) __nv_bfloat16 s_cat_hi[1536*Hc],  s_cat_lo[1536*Hc];   // [Wa | emb]
__device__ __align__(256) __nv_bfloat16 s_ws_hi[Hc*Hc],     s_ws_lo[Hc*Hc];

// ---------------- PTX helpers --------------------------------------------------
__device__ __forceinline__ uint smem_u32(const void* p){
    uint a; asm("{ .reg .u64 t; cvta.to.shared.u64 t, %1; cvt.u32.u64 %0, t; }" : "=r"(a) : "l"(p));
    return a;
}
__device__ __forceinline__ float tanha(float x){
    float y; asm("tanh.approx.f32 %0, %1;" : "=f"(y) : "f"(x)); return y;
}
__device__ __forceinline__ void cpa16(uint s, const void* g){
    asm volatile("cp.async.cg.shared.global [%0], [%1], 16;" :: "r"(s), "l"(g));
}
__device__ __forceinline__ void ldm4(uint addr, uint &r0, uint &r1, uint &r2, uint &r3){
    asm volatile("ldmatrix.sync.aligned.m8n8.x4.shared.b16 {%0,%1,%2,%3}, [%4];"
        : "=r"(r0), "=r"(r1), "=r"(r2), "=r"(r3) : "r"(addr));
}
__device__ __forceinline__ void mma16816(float* c, uint a0, uint a1, uint a2, uint a3,
                                         uint b0, uint b1){
    asm volatile("mma.sync.aligned.m16n8k16.row.col.f32.bf16.bf16.f32 "
        "{%0,%1,%2,%3}, {%4,%5,%6,%7}, {%8,%9}, {%0,%1,%2,%3};"
        : "+f"(c[0]), "+f"(c[1]), "+f"(c[2]), "+f"(c[3])
        : "r"(a0), "r"(a1), "r"(a2), "r"(a3), "r"(b0), "r"(b1));
}

// ---------------- grid-wide barrier (reset per launch by zero_bar) -------------
__device__ __forceinline__ void gbar(uint &gen){
    __threadfence();
    __syncthreads();
    if (threadIdx.x == 0){
        uint t = atomicAdd(&g_bar_count, 1);
        if (t == gridDim.x - 1){
            atomicExch(&g_bar_count, 0);
            __threadfence();
            atomicExch(&g_bar_gen, gen + 1);
        } else {
            while (atomicAdd(&g_bar_gen, 0) <= gen) __nanosleep(64);
        }
    }
    gen++;
    __syncthreads();
    __threadfence();
}

__global__ void zero_bar(){ g_bar_count = 0; g_bar_gen = 0; }

// ---------------- smem layout (bf16 elems, padded stride 72) -------------------
#define APITCH 72
#define A_ELE (128*APITCH)
#define B_ELE (32*APITCH)
#define SM_AHI 0
#define SM_ALO (SM_AHI + 2*A_ELE)
#define SM_BHI (SM_ALO + 2*A_ELE)
#define SM_BLO (SM_BHI + 2*B_ELE)
#define SM_ELE (SM_BLO + 2*B_ELE)
#define SM_DYN (SM_ELE*2)                 // 92160 bytes

// ---------------- weight f32 -> bf16 hi/lo -------------------------------------
__global__ void conv_hl(const float* __restrict__ src, __nv_bfloat16* __restrict__ hi,
                        __nv_bfloat16* __restrict__ lo, int n){
    for (int i = blockIdx.x*256 + threadIdx.x; i < n; i += gridDim.x*256){
        float x = src[i];
        __nv_bfloat16 h = __float2bfloat16(x);
        hi[i] = h;
        lo[i] = __float2bfloat16(x - __bfloat162float(h));
    }
}

// ---------------- HMMA GEMM tile (verified R7 body) ----------------------------
// out[32, .] = B @ A^T ; A bf16 hi/lo [col][Astride]; B f32 [row][Bstride].
// mode 0: out[(rowBase+n)*ldo + col] (+bias, opt tanh)
// mode 1: g_part[(zIdx*Ncols + col)*32 + n]
// mode 2: col<1024 -> g_sWa ; col>=1024 -> +bias into g_xs & g_moin (emb slots)
__device__ void gemm_tile(__nv_bfloat16* smem, int mode,
        const __nv_bfloat16* __restrict__ Ahi, const __nv_bfloat16* __restrict__ Alo,
        int Astride, int NC, int Akoff,
        const float* __restrict__ Bsrc, int Bstride, int Bkoff,
        const float* __restrict__ bias, float* __restrict__ out, long ldo,
        int Ncols, int zIdx, int colBase, int rowBase, int act)
{
    const int tid  = threadIdx.x;
    const int lane = tid & 31;
    const int warp = tid >> 5;
    const uint sb  = smem_u32(smem);

    float acc[4][4];
#pragma unroll
    for (int nt = 0; nt < 4; nt++)
#pragma unroll
        for (int q = 0; q < 4; q++) acc[nt][q] = 0.f;

    auto prefA = [&](int c, int bi){
#pragma unroll
        for (int i = 0; i < 4; i++){
            int f  = tid + i*256;
            int r  = f >> 3, kc = f & 7;
            size_t so = (size_t)(colBase + r)*Astride + Akoff + c*64 + kc*8;
            uint dst = (uint)((r*APITCH + kc*8)*2);
            cpa16(sb + (SM_AHI + bi*A_ELE)*2 + dst, Ahi + so);
            cpa16(sb + (SM_ALO + bi*A_ELE)*2 + dst, Alo + so);
        }
        asm volatile("cp.async.commit_group;");
    };
    auto convB = [&](int c, int bi){
        int r  = tid >> 3, k0 = (tid & 7)*8;
        const float* src = Bsrc + (size_t)(rowBase + r)*Bstride + Bkoff + c*64 + k0;
        float4 f0 = *(const float4*)(src);
        float4 f1 = *(const float4*)(src + 4);
        float xs8[8] = {f0.x, f0.y, f0.z, f0.w, f1.x, f1.y, f1.z, f1.w};
        __nv_bfloat16 h8[8], l8[8];
#pragma unroll
        for (int j = 0; j < 8; j++){
            h8[j] = __float2bfloat16(xs8[j]);
            l8[j] = __float2bfloat16(xs8[j] - __bfloat162float(h8[j]));
        }
        *(uint4*)(&smem[SM_BHI + bi*B_ELE + r*APITCH + k0]) = *(uint4*)h8;
        *(uint4*)(&smem[SM_BLO + bi*B_ELE + r*APITCH + k0]) = *(uint4*)l8;
    };

    prefA(0, 0);
    convB(0, 0);

    const int i8   = lane & 7;
    const int quad = lane >> 3;
    const uint aoff = (uint)(((warp*16 + i8 + (quad&1)*8)*APITCH + (quad>>1)*8)*2);
    const uint boff = (uint)((((quad>>1)*8 + i8)*APITCH + (quad&1)*8)*2);

    for (int c = 0; c < NC; c++){
        int bi = c & 1;
        if (c + 1 < NC){
            prefA(c + 1, bi ^ 1);
            convB(c + 1, bi ^ 1);
            asm volatile("cp.async.wait_group 1;");
        } else {
            asm volatile("cp.async.wait_group 0;");
        }
        __syncthreads();

        uint aHi = sb + (SM_AHI + bi*A_ELE)*2 + aoff;
        uint aLo = sb + (SM_ALO + bi*A_ELE)*2 + aoff;
        uint bHi = sb + (SM_BHI + bi*B_ELE)*2 + boff;
        uint bLo = sb + (SM_BLO + bi*B_ELE)*2 + boff;

#pragma unroll
        for (int ks = 0; ks < 4; ks++){
            uint kd = (uint)(ks*16*2);
            uint ah[4], al[4], bh0[4], bh1[4], bl0[4], bl1[4];
            ldm4(aHi + kd, ah[0], ah[1], ah[2], ah[3]);
            ldm4(aLo + kd, al[0], al[1], al[2], al[3]);
            ldm4(bHi + kd,               bh0[0], bh0[1], bh0[2], bh0[3]);
            ldm4(bHi + kd + 16*APITCH*2, bh1[0], bh1[1], bh1[2], bh1[3]);
            ldm4(bLo + kd,               bl0[0], bl0[1], bl0[2], bl0[3]);
            ldm4(bLo + kd + 16*APITCH*2, bl1[0], bl1[1], bl1[2], bl1[3]);
            mma16816(acc[0], ah[0],ah[1],ah[2],ah[3], bh0[0], bh0[1]);
            mma16816(acc[1], ah[0],ah[1],ah[2],ah[3], bh0[2], bh0[3]);
            mma16816(acc[2], ah[0],ah[1],ah[2],ah[3], bh1[0], bh1[1]);
            mma16816(acc[3], ah[0],ah[1],ah[2],ah[3], bh1[2], bh1[3]);
            mma16816(acc[0], ah[0],ah[1],ah[2],ah[3], bl0[0], bl0[1]);
            mma16816(acc[1], ah[0],ah[1],ah[2],ah[3], bl0[2], bl0[3]);
            mma16816(acc[2], ah[0],ah[1],ah[2],ah[3], bl1[0], bl1[1]);
            mma16816(acc[3], ah[0],ah[1],ah[2],ah[3], bl1[2], bl1[3]);
            mma16816(acc[0], al[0],al[1],al[2],al[3], bh0[0], bh0[1]);
            mma16816(acc[1], al[0],al[1],al[2],al[3], bh0[2], bh0[3]);
            mma16816(acc[2], al[0],al[1],al[2],al[3], bh1[0], bh1[1]);
            mma16816(acc[3], al[0],al[1],al[2],al[3], bh1[2], bh1[3]);
        }
        __syncthreads();
    }

    const int g   = lane >> 2;
    const int tig = lane & 3;
#pragma unroll
    for (int nt = 0; nt < 4; nt++){
#pragma unroll
        for (int q = 0; q < 4; q++){
            int colm = colBase + warp*16 + g + ((q >> 1) ? 8 : 0);
            int n    = nt*8 + 2*tig + (q & 1);
            float v  = acc[nt][q];
            if (mode == 0){
                v += bias ? bias[colm] : 0.f;
                if (act) v = tanhf(v);
                out[(size_t)(rowBase + n)*ldo + colm] = v;
            } else if (mode == 1){
                g_part[((size_t)zIdx*Ncols + colm)*32 + n] = v;
            } else {
                if (colm < 1024){
                    g_sWa[n*1024 + colm] = v;
                } else {
                    int c2 = colm - 1024;
                    float o = v + bias[c2];
                    g_xs[n*3584 + c2] = o;
                    g_moin[n*3584 + 3072 + c2] = o;
                }
            }
        }
    }
}

// global wrapper for setup GEMMs
__global__ void __launch_bounds__(256) hm_gemm0(
        const __nv_bfloat16* Ahi, const __nv_bfloat16* Alo, int Astride, int NC,
        const float* Bsrc, int Bstride, const float* bias, float* out, long ldo, int act)
{
    extern __shared__ __nv_bfloat16 smem[];
    gemm_tile(smem, 0, Ahi, Alo, Astride, NC, 0, Bsrc, Bstride, 0,
              bias, out, ldo, 0, 0, blockIdx.x*128, blockIdx.y*32, act);
}

// ---------------- attention block (b = one batch row) --------------------------
__device__ void attn_block(__nv_bfloat16* smraw, int b, const float* __restrict__ enc_out,
                           const float* __restrict__ va, float* __restrict__ alphas, int tstep){
    float* fs  = (float*)smraw;
    float* sW  = fs;            // 1024
    float* sva = fs + 1024;     // 1024
    float* sal = fs + 2048;     // 64
    float* sinv = fs + 2112;
    int tid = threadIdx.x, lane = tid & 31, warp = tid >> 5;

    for (int k = tid; k < Hc; k += 256){
        sW[k]  = g_sWa[b*Hc + k];
        sva[k] = va[k];
    }
    __syncthreads();

    for (int j = 0; j < 8; j++){
        int t = warp*8 + j;
        const float4* ur = (const float4*)(g_Ua + (size_t)(b*Tc + t)*Hc);
        float p = 0.f;
#pragma unroll
        for (int q = 0; q < 8; q++){
            int i = q*32 + lane;
            float4 u = ur[i];
            float4 s = *(const float4*)&sW[i*4];
            float4 v = *(const float4*)&sva[i*4];
            p += v.x*tanha(s.x+u.x) + v.y*tanha(s.y+u.y)
               + v.z*tanha(s.z+u.z) + v.w*tanha(s.w+u.w);
        }
#pragma unroll
        for (int o = 16; o > 0; o >>= 1) p += __shfl_xor_sync(0xffffffffu, p, o);
        if (lane == 0) sal[t] = p;
    }
    __syncthreads();
    if (tid == 0){
        float mx = -1e30f;
        for (int t = 0; t < Tc; t++) mx = fmaxf(mx, sal[t]);
        float s = 0.f;
        for (int t = 0; t < Tc; t++){ float ev = __expf(sal[t] - mx); sal[t] = ev; s += ev; }
        *sinv = 1.f / s;
    }
    __syncthreads();
    if (tid < Tc) sal[tid] *= *sinv;
    __syncthreads();
    if (tid < Tc)
        alphas[((size_t)b*Tc + tstep)*Tc + tid] = sal[tid];

    const float4* eo = (const float4*)(enc_out + (size_t)b*Tc*2*Hc);
    for (int f4 = tid; f4 < (2*Hc)/4; f4 += 256){
        float4 acc = make_float4(0.f, 0.f, 0.f, 0.f);
        for (int t = 0; t < Tc; t++){
            float al = sal[t];
            float4 ev = eo[(size_t)t*(2*Hc/4) + f4];
            acc.x += al*ev.x; acc.y += al*ev.y; acc.z += al*ev.z; acc.w += al*ev.w;
        }
        int f = f4*4;
        *(float4*)&g_xs[b*3584 + Ec + f]   = acc;
        *(float4*)&g_moin[b*3584 + Hc + f] = acc;
    }
}

// ---------------- persistent megakernel ----------------------------------------
__global__ void __launch_bounds__(256) mega(
        const float* __restrict__ enc_out, const float* __restrict__ va,
        const float* __restrict__ emb_b, const float* __restrict__ b_ih,
        const float* __restrict__ b_hh, const float* __restrict__ mo_b,
        const float* __restrict__ fc_b, float* __restrict__ logits,
        float* __restrict__ alphas)
{
    extern __shared__ __nv_bfloat16 smem[];
    const int tid  = threadIdx.x;
    const int gtid = blockIdx.x*256 + tid;
    uint gen = 0;

    for (int t = 0; t < Tc; t++){
        // -- A: PRE  [Wa | emb](1536 cols) @ si  (12 tiles)
        for (int j = blockIdx.x; j < 12; j += gridDim.x){
            int colBase = j*128;
            if (t == 0 && colBase >= 1024){
                for (int i = tid; i < 128*32; i += 256){
                    int c2 = colBase - 1024 + (i >> 5);
                    int b  = i & 31;
                    float v = emb_b[c2];
                    g_xs[b*3584 + c2] = v;
                    g_moin[b*3584 + 3072 + c2] = v;
                }
            } else {
                gemm_tile(smem, 2, s_cat_hi, s_cat_lo, Hc, 16, 0,
                          g_xs, 3584, 2560, emb_b, nullptr, 0, 0, 0, colBase, 0, 0);
            }
        }
        gbar(gen);
        // -- B: attention (energies + softmax + context)
        if (blockIdx.x < 32)
            attn_block(smem, blockIdx.x, enc_out, va, alphas, t);
        gbar(gen);
        // -- C: gates  (ih: 96 jobs, hh: 48 jobs)
        for (int j = blockIdx.x; j < 144; j += gridDim.x){
            if (j < 96){
                int x = j % 24, z = j / 24;
                gemm_tile(smem, 1, s_ih_hi, s_ih_lo, 2560, 10, z*640,
                          g_xs, 3584, z*640, nullptr, nullptr, 0, 3*Hc, z, x*128, 0, 0);
            } else {
                int jj = j - 96; int x = jj % 24, z = jj / 24;
                gemm_tile(smem, 1, s_hh_hi, s_hh_lo, 1024, 8, z*512,
                          g_xs, 3584, 2560 + z*512, nullptr, nullptr, 0, 3*Hc, 4 + z, x*128, 0, 0);
            }
        }
        gbar(gen);
        // -- D: split-K reduce + GRU gates
        if (gtid < Hc*32){
            int b = gtid & 31, col = gtid >> 5;
            float xr = 0.f, xz = 0.f, xn = 0.f, hr = 0.f, hz = 0.f, hn = 0.f;
#pragma unroll
            for (int z = 0; z < 4; z++){
                size_t ba = (size_t)z*3*Hc*32;
                xr += g_part[ba + (size_t)(col)*32        + b];
                xz += g_part[ba + (size_t)(Hc + col)*32   + b];
                xn += g_part[ba + (size_t)(2*Hc + col)*32 + b];
            }
#pragma unroll
            for (int z = 4; z < 6; z++){
                size_t ba = (size_t)z*3*Hc*32;
                hr += g_part[ba + (size_t)(col)*32        + b];
                hz += g_part[ba + (size_t)(Hc + col)*32   + b];
                hn += g_part[ba + (size_t)(2*Hc + col)*32 + b];
            }
            xr += b_ih[col];        hr += b_hh[col];
            xz += b_ih[Hc + col];   hz += b_hh[Hc + col];
            xn += b_ih[2*Hc + col]; hn += b_hh[2*Hc + col];
            float r = 1.f/(1.f + __expf(-(xr + hr)));
            float z = 1.f/(1.f + __expf(-(xz + hz)));
            float n = tanhf(xn + r*hn);
            float s  = g_xs[b*3584 + 2560 + col];
            float sn = (1.f - z)*n + z*s;
            g_xs[b*3584 + 2560 + col] = sn;
            g_moin[b*3584 + col]      = sn;
        }
        gbar(gen);
        // -- E: maxout GEMM partials (32 jobs)
        for (int j = blockIdx.x; j < 32; j += gridDim.x){
            int x = j % 8, z = j / 8;
            gemm_tile(smem, 1, s_mo_hi, s_mo_lo, 3584, 14, z*896,
                      g_moin, 3584, z*896, nullptr, nullptr, 0, 2*Mc, z, x*128, 0, 0);
        }
        gbar(gen);
        // -- F: maxout reduce
        if (gtid < Mc*32){
            int b = gtid & 31, m = gtid >> 5;
            float s0 = 0.f, s1 = 0.f;
#pragma unroll
            for (int z = 0; z < 4; z++){
                size_t ba = (size_t)z*2*Mc*32;
                s0 += g_part[ba + (size_t)(2*m)*32   + b];
                s1 += g_part[ba + (size_t)(2*m+1)*32 + b];
            }
            g_m[b*Mc + m] = fmaxf(s0 + mo_b[2*m], s1 + mo_b[2*m + 1]);
        }
        gbar(gen);
        // -- G: fc logits (250 jobs)
        for (int j = blockIdx.x; j < 250; j += gridDim.x){
            gemm_tile(smem, 0, s_fc_hi, s_fc_lo, 512, 8, 0,
                      g_m, 512, 0, fc_b, logits + (size_t)t*Vc, (long)Tc*Vc,
                      0, 0, j*128, 0, 0);
        }
        gbar(gen);
    }
}

// ---------------- launch --------------------------------------------------------
extern "C" void kernel_launch(void* const* d_in, const int* in_sizes, int n_in,
                              void* d_out, int out_size)
{
    const float* enc_out = (const float*)d_in[0];
    const float* hidden  = (const float*)d_in[1];
    const float* Ws_w    = (const float*)d_in[2];
    const float* Ws_b    = (const float*)d_in[3];
    const float* emb_w   = (const float*)d_in[4];
    const float* emb_b   = (const float*)d_in[5];
    const float* w_ih    = (const float*)d_in[6];
    const float* w_hh    = (const float*)d_in[7];
    const float* b_ih    = (const float*)d_in[8];
    const float* b_hh    = (const float*)d_in[9];
    const float* Wa      = (const float*)d_in[10];
    const float* Ua      = (const float*)d_in[11];
    const float* va      = (const float*)d_in[12];
    const float* mo_w    = (const float*)d_in[13];
    const float* mo_b    = (const float*)d_in[14];
    const float* fc_w    = (const float*)d_in[15];
    const float* fc_b    = (const float*)d_in[16];

    float* logits = (float*)d_out;
    float* alphas = logits + (size_t)Bc*Tc*Vc;

    float *pxs, *pUa;
    __nv_bfloat16 *fc_h, *fc_l, *ih_h, *ih_l, *hh_h, *hh_l, *mo_h, *mo_l,
                  *ua_h, *ua_l, *cat_h, *cat_l, *ws_h, *ws_l;
    cudaGetSymbolAddress((void**)&pxs,   g_xs);
    cudaGetSymbolAddress((void**)&pUa,   g_Ua);
    cudaGetSymbolAddress((void**)&fc_h,  s_fc_hi);  cudaGetSymbolAddress((void**)&fc_l,  s_fc_lo);
    cudaGetSymbolAddress((void**)&ih_h,  s_ih_hi);  cudaGetSymbolAddress((void**)&ih_l,  s_ih_lo);
    cudaGetSymbolAddress((void**)&hh_h,  s_hh_hi);  cudaGetSymbolAddress((void**)&hh_l,  s_hh_lo);
    cudaGetSymbolAddress((void**)&mo_h,  s_mo_hi);  cudaGetSymbolAddress((void**)&mo_l,  s_mo_lo);
    cudaGetSymbolAddress((void**)&ua_h,  s_ua_hi);  cudaGetSymbolAddress((void**)&ua_l,  s_ua_lo);
    cudaGetSymbolAddress((void**)&cat_h, s_cat_hi); cudaGetSymbolAddress((void**)&cat_l, s_cat_lo);
    cudaGetSymbolAddress((void**)&ws_h,  s_ws_hi);  cudaGetSymbolAddress((void**)&ws_l,  s_ws_lo);

    cudaFuncSetAttribute(hm_gemm0, cudaFuncAttributeMaxDynamicSharedMemorySize, SM_DYN);
    cudaFuncSetAttribute(mega,     cudaFuncAttributeMaxDynamicSharedMemorySize, SM_DYN);

    // ---- one-time weight conversion
    conv_hl<<<2048, 256>>>(fc_w,  fc_h,  fc_l,  Vc*Mc);
    conv_hl<<<2048, 256>>>(w_ih,  ih_h,  ih_l,  3*Hc*2560);
    conv_hl<<<1024, 256>>>(w_hh,  hh_h,  hh_l,  3*Hc*Hc);
    conv_hl<<<1024, 256>>>(mo_w,  mo_h,  mo_l,  2*Mc*3584);
    conv_hl<<<1024, 256>>>(Ua,    ua_h,  ua_l,  Hc*2*Hc);
    conv_hl<<<512,  256>>>(Wa,    cat_h, cat_l, Hc*Hc);
    conv_hl<<<512,  256>>>(emb_w, cat_h + (size_t)Hc*Hc, cat_l + (size_t)Hc*Hc, Ec*Hc);
    conv_hl<<<512,  256>>>(Ws_w,  ws_h,  ws_l,  Hc*Hc);

    // ---- si0 = tanh(hidden[1] @ Ws_w^T + Ws_b) -> xs si slot
    hm_gemm0<<<dim3(8,1,1), 256, SM_DYN>>>(ws_h, ws_l, Hc, 16,
        hidden + Bc*Hc, Hc, Ws_b, pxs + 2560, 3584, 1);
    // ---- Ua_enc = enc_out @ Ua^T -> g_Ua[bt][a]
    hm_gemm0<<<dim3(8,64,1), 256, SM_DYN>>>(ua_h, ua_l, 2*Hc, 32,
        enc_out, 2*Hc, nullptr, pUa, Hc, 0);

    // ---- reset barrier state, run all 64 steps in one persistent kernel
    zero_bar<<<1, 1>>>();
    mega<<<NBLK, 256, SM_DYN>>>(enc_out, va, emb_b, b_ih, b_hh, mo_b, fc_b,
                                logits, alphas);
}

// round 10
// speedup vs baseline: 4.1681x; 1.4432x over previous
#include <cuda_runtime.h>
#include <cuda_bf16.h>
#include <math.h>

#define Bc 32
#define Tc 64
#define Hc 1024
#define Ec 512
#define Mc 512
#define Vc 32000
#define NBLK 146

typedef unsigned int uint;
typedef unsigned long long ull;

// ---------------- f32 scratch --------------------------------------------------
__device__ __align__(256) float g_sWa[Bc*Hc];
__device__ __align__(256) float g_Ua[Bc*Tc*Hc];
__device__ __align__(256) float g_xs[Bc*3584];    // [b][ emb 0:512 | ctx 512:2560 | si 2560:3584 ]
__device__ __align__(256) float g_moin[Bc*3584];  // [b][ si 0:1024 | ctx 1024:3072 | emb 3072:3584 ]
__device__ __align__(256) float g_m[Bc*Mc];
__device__ __align__(256) float g_part[7*3072*32];  // split-K partials

__device__ uint g_bar_count;
__device__ uint g_bar_gen;

// ---------------- bf16 hi/lo weights -------------------------------------------
__device__ __align__(256) __nv_bfloat16 s_fc_hi[Vc*Mc],     s_fc_lo[Vc*Mc];
__device__ __align__(256) __nv_bfloat16 s_ih_hi[3*Hc*2560], s_ih_lo[3*Hc*2560];
__device__ __align__(256) __nv_bfloat16 s_hh_hi[3*Hc*Hc],   s_hh_lo[3*Hc*Hc];
__device__ __align__(256) __nv_bfloat16 s_mo_hi[2*Mc*3584], s_mo_lo[2*Mc*3584];
__device__ __align__(256) __nv_bfloat16 s_ua_hi[Hc*2*Hc],   s_ua_lo[Hc*2*Hc];
__device__ __align__(256) __nv_bfloat16 s_cat_hi[1536*Hc],  s_cat_lo[1536*Hc];   // [Wa | emb]
__device__ __align__(256) __nv_bfloat16 s_ws_hi[Hc*Hc],     s_ws_lo[Hc*Hc];

// ---------------- PTX helpers --------------------------------------------------
__device__ __forceinline__ uint smem_u32(const void* p){
    uint a; asm("{ .reg .u64 t; cvta.to.shared.u64 t, %1; cvt.u32.u64 %0, t; }" : "=r"(a) : "l"(p));
    return a;
}
__device__ __forceinline__ float tanha(float x){
    float y; asm("tanh.approx.f32 %0, %1;" : "=f"(y) : "f"(x)); return y;
}
__device__ __forceinline__ void cpa16(uint s, const void* g){
    asm volatile("cp.async.cg.shared.global [%0], [%1], 16;" :: "r"(s), "l"(g));
}
__device__ __forceinline__ void ldm4(uint addr, uint &r0, uint &r1, uint &r2, uint &r3){
    asm volatile("ldmatrix.sync.aligned.m8n8.x4.shared.b16 {%0,%1,%2,%3}, [%4];"
        : "=r"(r0), "=r"(r1), "=r"(r2), "=r"(r3) : "r"(addr));
}
__device__ __forceinline__ void mma16816(float* c, uint a0, uint a1, uint a2, uint a3,
                                         uint b0, uint b1){
    asm volatile("mma.sync.aligned.m16n8k16.row.col.f32.bf16.bf16.f32 "
        "{%0,%1,%2,%3}, {%4,%5,%6,%7}, {%8,%9}, {%0,%1,%2,%3};"
        : "+f"(c[0]), "+f"(c[1]), "+f"(c[2]), "+f"(c[3])
        : "r"(a0), "r"(a1), "r"(a2), "r"(a3), "r"(b0), "r"(b1));
}

// ---------------- grid-wide barrier: atomic arrive, VOLATILE-LOAD spin ---------
__device__ __forceinline__ void gbar(uint &gen){
    __threadfence();
    __syncthreads();
    if (threadIdx.x == 0){
        uint t = atomicAdd(&g_bar_count, 1);
        if (t == gridDim.x - 1){
            atomicExch(&g_bar_count, 0);
            __threadfence();
            atomicExch(&g_bar_gen, gen + 1);
        } else {
            while (*(volatile uint*)&g_bar_gen <= gen) __nanosleep(32);
        }
    }
    gen++;
    __syncthreads();
    __threadfence();
}

__global__ void zero_bar(){ g_bar_count = 0; g_bar_gen = 0; }

// ---------------- smem layout (bf16 elems, padded stride 72) -------------------
#define APITCH 72
#define A_ELE (128*APITCH)
#define B_ELE (32*APITCH)
#define SM_AHI 0
#define SM_ALO (SM_AHI + 2*A_ELE)
#define SM_BHI (SM_ALO + 2*A_ELE)
#define SM_BLO (SM_BHI + 2*B_ELE)
#define SM_ELE (SM_BLO + 2*B_ELE)
#define SM_DYN (SM_ELE*2)                 // 92160 bytes

// ---------------- weight f32 -> bf16 hi/lo -------------------------------------
__global__ void conv_hl(const float* __restrict__ src, __nv_bfloat16* __restrict__ hi,
                        __nv_bfloat16* __restrict__ lo, int n){
    for (int i = blockIdx.x*256 + threadIdx.x; i < n; i += gridDim.x*256){
        float x = src[i];
        __nv_bfloat16 h = __float2bfloat16(x);
        hi[i] = h;
        lo[i] = __float2bfloat16(x - __bfloat162float(h));
    }
}

// ---------------- HMMA GEMM tile (verified R7 body) ----------------------------
// out[32, .] = B @ A^T ; A bf16 hi/lo [col][Astride]; B f32 [row][Bstride].
// mode 0: out[(rowBase+n)*ldo + col] (+bias, opt tanh)
// mode 1: g_part[(zIdx*Ncols + col)*32 + n]
// mode 2: col<1024 -> g_sWa ; col>=1024 -> +bias into g_xs & g_moin (emb slots)
__device__ void gemm_tile(__nv_bfloat16* smem, int mode,
        const __nv_bfloat16* __restrict__ Ahi, const __nv_bfloat16* __restrict__ Alo,
        int Astride, int NC, int Akoff,
        const float* __restrict__ Bsrc, int Bstride, int Bkoff,
        const float* __restrict__ bias, float* __restrict__ out, long ldo,
        int Ncols, int zIdx, int colBase, int rowBase, int act)
{
    const int tid  = threadIdx.x;
    const int lane = tid & 31;
    const int warp = tid >> 5;
    const uint sb  = smem_u32(smem);

    float acc[4][4];
#pragma unroll
    for (int nt = 0; nt < 4; nt++)
#pragma unroll
        for (int q = 0; q < 4; q++) acc[nt][q] = 0.f;

    auto prefA = [&](int c, int bi){
#pragma unroll
        for (int i = 0; i < 4; i++){
            int f  = tid + i*256;
            int r  = f >> 3, kc = f & 7;
            size_t so = (size_t)(colBase + r)*Astride + Akoff + c*64 + kc*8;
            uint dst = (uint)((r*APITCH + kc*8)*2);
            cpa16(sb + (SM_AHI + bi*A_ELE)*2 + dst, Ahi + so);
            cpa16(sb + (SM_ALO + bi*A_ELE)*2 + dst, Alo + so);
        }
        asm volatile("cp.async.commit_group;");
    };
    auto convB = [&](int c, int bi){
        int r  = tid >> 3, k0 = (tid & 7)*8;
        const float* src = Bsrc + (size_t)(rowBase + r)*Bstride + Bkoff + c*64 + k0;
        float4 f0 = *(const float4*)(src);
        float4 f1 = *(const float4*)(src + 4);
        float xs8[8] = {f0.x, f0.y, f0.z, f0.w, f1.x, f1.y, f1.z, f1.w};
        __nv_bfloat16 h8[8], l8[8];
#pragma unroll
        for (int j = 0; j < 8; j++){
            h8[j] = __float2bfloat16(xs8[j]);
            l8[j] = __float2bfloat16(xs8[j] - __bfloat162float(h8[j]));
        }
        *(uint4*)(&smem[SM_BHI + bi*B_ELE + r*APITCH + k0]) = *(uint4*)h8;
        *(uint4*)(&smem[SM_BLO + bi*B_ELE + r*APITCH + k0]) = *(uint4*)l8;
    };

    prefA(0, 0);
    convB(0, 0);

    const int i8   = lane & 7;
    const int quad = lane >> 3;
    const uint aoff = (uint)(((warp*16 + i8 + (quad&1)*8)*APITCH + (quad>>1)*8)*2);
    const uint boff = (uint)((((quad>>1)*8 + i8)*APITCH + (quad&1)*8)*2);

    for (int c = 0; c < NC; c++){
        int bi = c & 1;
        if (c + 1 < NC){
            prefA(c + 1, bi ^ 1);
            convB(c + 1, bi ^ 1);
            asm volatile("cp.async.wait_group 1;");
        } else {
            asm volatile("cp.async.wait_group 0;");
        }
        __syncthreads();

        uint aHi = sb + (SM_AHI + bi*A_ELE)*2 + aoff;
        uint aLo = sb + (SM_ALO + bi*A_ELE)*2 + aoff;
        uint bHi = sb + (SM_BHI + bi*B_ELE)*2 + boff;
        uint bLo = sb + (SM_BLO + bi*B_ELE)*2 + boff;

#pragma unroll
        for (int ks = 0; ks < 4; ks++){
            uint kd = (uint)(ks*16*2);
            uint ah[4], al[4], bh0[4], bh1[4], bl0[4], bl1[4];
            ldm4(aHi + kd, ah[0], ah[1], ah[2], ah[3]);
            ldm4(aLo + kd, al[0], al[1], al[2], al[3]);
            ldm4(bHi + kd,               bh0[0], bh0[1], bh0[2], bh0[3]);
            ldm4(bHi + kd + 16*APITCH*2, bh1[0], bh1[1], bh1[2], bh1[3]);
            ldm4(bLo + kd,               bl0[0], bl0[1], bl0[2], bl0[3]);
            ldm4(bLo + kd + 16*APITCH*2, bl1[0], bl1[1], bl1[2], bl1[3]);
            mma16816(acc[0], ah[0],ah[1],ah[2],ah[3], bh0[0], bh0[1]);
            mma16816(acc[1], ah[0],ah[1],ah[2],ah[3], bh0[2], bh0[3]);
            mma16816(acc[2], ah[0],ah[1],ah[2],ah[3], bh1[0], bh1[1]);
            mma16816(acc[3], ah[0],ah[1],ah[2],ah[3], bh1[2], bh1[3]);
            mma16816(acc[0], ah[0],ah[1],ah[2],ah[3], bl0[0], bl0[1]);
            mma16816(acc[1], ah[0],ah[1],ah[2],ah[3], bl0[2], bl0[3]);
            mma16816(acc[2], ah[0],ah[1],ah[2],ah[3], bl1[0], bl1[1]);
            mma16816(acc[3], ah[0],ah[1],ah[2],ah[3], bl1[2], bl1[3]);
            mma16816(acc[0], al[0],al[1],al[2],al[3], bh0[0], bh0[1]);
            mma16816(acc[1], al[0],al[1],al[2],al[3], bh0[2], bh0[3]);
            mma16816(acc[2], al[0],al[1],al[2],al[3], bh1[0], bh1[1]);
            mma16816(acc[3], al[0],al[1],al[2],al[3], bh1[2], bh1[3]);
        }
        __syncthreads();
    }

    const int g   = lane >> 2;
    const int tig = lane & 3;
#pragma unroll
    for (int nt = 0; nt < 4; nt++){
#pragma unroll
        for (int q = 0; q < 4; q++){
            int colm = colBase + warp*16 + g + ((q >> 1) ? 8 : 0);
            int n    = nt*8 + 2*tig + (q & 1);
            float v  = acc[nt][q];
            if (mode == 0){
                v += bias ? bias[colm] : 0.f;
                if (act) v = tanhf(v);
                out[(size_t)(rowBase + n)*ldo + colm] = v;
            } else if (mode == 1){
                g_part[((size_t)zIdx*Ncols + colm)*32 + n] = v;
            } else {
                if (colm < 1024){
                    g_sWa[n*1024 + colm] = v;
                } else {
                    int c2 = colm - 1024;
                    float o = v + bias[c2];
                    g_xs[n*3584 + c2] = o;
                    g_moin[n*3584 + 3072 + c2] = o;
                }
            }
        }
    }
}

// global wrapper for setup GEMMs
__global__ void __launch_bounds__(256) hm_gemm0(
        const __nv_bfloat16* Ahi, const __nv_bfloat16* Alo, int Astride, int NC,
        const float* Bsrc, int Bstride, const float* bias, float* out, long ldo, int act)
{
    extern __shared__ __nv_bfloat16 smem[];
    gemm_tile(smem, 0, Ahi, Alo, Astride, NC, 0, Bsrc, Bstride, 0,
              bias, out, ldo, 0, 0, blockIdx.x*128, blockIdx.y*32, act);
}

// ---------------- attention block (b = one batch row) --------------------------
__device__ void attn_block(__nv_bfloat16* smraw, int b, const float* __restrict__ enc_out,
                           const float* __restrict__ va, float* __restrict__ alphas, int tstep){
    float* fs  = (float*)smraw;
    float* sW  = fs;            // 1024
    float* sva = fs + 1024;     // 1024
    float* sal = fs + 2048;     // 64
    float* sinv = fs + 2112;
    int tid = threadIdx.x, lane = tid & 31, warp = tid >> 5;

    for (int k = tid; k < Hc; k += 256){
        sW[k]  = g_sWa[b*Hc + k];
        sva[k] = va[k];
    }
    __syncthreads();

    for (int j = 0; j < 8; j++){
        int t = warp*8 + j;
        const float4* ur = (const float4*)(g_Ua + (size_t)(b*Tc + t)*Hc);
        float p = 0.f;
#pragma unroll
        for (int q = 0; q < 8; q++){
            int i = q*32 + lane;
            float4 u = ur[i];
            float4 s = *(const float4*)&sW[i*4];
            float4 v = *(const float4*)&sva[i*4];
            p += v.x*tanha(s.x+u.x) + v.y*tanha(s.y+u.y)
               + v.z*tanha(s.z+u.z) + v.w*tanha(s.w+u.w);
        }
#pragma unroll
        for (int o = 16; o > 0; o >>= 1) p += __shfl_xor_sync(0xffffffffu, p, o);
        if (lane == 0) sal[t] = p;
    }
    __syncthreads();
    if (tid == 0){
        float mx = -1e30f;
        for (int t = 0; t < Tc; t++) mx = fmaxf(mx, sal[t]);
        float s = 0.f;
        for (int t = 0; t < Tc; t++){ float ev = __expf(sal[t] - mx); sal[t] = ev; s += ev; }
        *sinv = 1.f / s;
    }
    __syncthreads();
    if (tid < Tc) sal[tid] *= *sinv;
    __syncthreads();
    if (tid < Tc)
        alphas[((size_t)b*Tc + tstep)*Tc + tid] = sal[tid];

    const float4* eo = (const float4*)(enc_out + (size_t)b*Tc*2*Hc);
    for (int f4 = tid; f4 < (2*Hc)/4; f4 += 256){
        float4 acc = make_float4(0.f, 0.f, 0.f, 0.f);
        for (int t = 0; t < Tc; t++){
            float al = sal[t];
            float4 ev = eo[(size_t)t*(2*Hc/4) + f4];
            acc.x += al*ev.x; acc.y += al*ev.y; acc.z += al*ev.z; acc.w += al*ev.w;
        }
        int f = f4*4;
        *(float4*)&g_xs[b*3584 + Ec + f]   = acc;
        *(float4*)&g_moin[b*3584 + Hc + f] = acc;
    }
}

// ---------------- persistent megakernel ----------------------------------------
// Per step, 6 barrier-separated stages:
//  S1: PRE(t) [blocks 0-11] + fc(t-1) [blocks 12-145, 250 jobs]
//  S2: attention(t) [blocks 0-31] + hh gate partials z5,6 [blocks 32-79]
//  S3: ih gate partials z0..4 (120 jobs)
//  S4: split-K reduce + GRU
//  S5: maxout partials z0..6 (56 jobs)
//  S6: maxout reduce
// After the loop: fc(63) on all blocks.
__global__ void __launch_bounds__(256) mega(
        const float* __restrict__ enc_out, const float* __restrict__ va,
        const float* __restrict__ emb_b, const float* __restrict__ b_ih,
        const float* __restrict__ b_hh, const float* __restrict__ mo_b,
        const float* __restrict__ fc_b, float* __restrict__ logits,
        float* __restrict__ alphas)
{
    extern __shared__ __nv_bfloat16 smem[];
    const int tid  = threadIdx.x;
    const int gtid = blockIdx.x*256 + tid;
    uint gen = 0;

    for (int t = 0; t < Tc; t++){
        // -- S1: PRE(t) + fc(t-1)
        if (blockIdx.x < 12){
            int colBase = blockIdx.x*128;
            if (t == 0 && colBase >= 1024){
                for (int i = tid; i < 128*32; i += 256){
                    int c2 = colBase - 1024 + (i >> 5);
                    int b  = i & 31;
                    float v = emb_b[c2];
                    g_xs[b*3584 + c2] = v;
                    g_moin[b*3584 + 3072 + c2] = v;
                }
            } else {
                gemm_tile(smem, 2, s_cat_hi, s_cat_lo, Hc, 16, 0,
                          g_xs, 3584, 2560, emb_b, nullptr, 0, 0, 0, colBase, 0, 0);
            }
        } else if (t > 0){
            for (int j = blockIdx.x - 12; j < 250; j += (gridDim.x - 12))
                gemm_tile(smem, 0, s_fc_hi, s_fc_lo, 512, 8, 0,
                          g_m, 512, 0, fc_b, logits + (size_t)(t-1)*Vc, (long)Tc*Vc,
                          0, 0, j*128, 0, 0);
        }
        gbar(gen);
        // -- S2: attention + hh partials (zIdx 5,6)
        if (blockIdx.x < 32){
            attn_block(smem, blockIdx.x, enc_out, va, alphas, t);
        } else if (blockIdx.x < 80){
            int j = blockIdx.x - 32;      // 0..47
            int x = j % 24, z = j / 24;   // z in {0,1}
            gemm_tile(smem, 1, s_hh_hi, s_hh_lo, 1024, 8, z*512,
                      g_xs, 3584, 2560 + z*512, nullptr, nullptr, 0, 3*Hc, 5 + z, x*128, 0, 0);
        }
        gbar(gen);
        // -- S3: ih partials (zIdx 0..4, 120 jobs)
        for (int j = blockIdx.x; j < 120; j += gridDim.x){
            int x = j % 24, z = j / 24;
            gemm_tile(smem, 1, s_ih_hi, s_ih_lo, 2560, 8, z*512,
                      g_xs, 3584, z*512, nullptr, nullptr, 0, 3*Hc, z, x*128, 0, 0);
        }
        gbar(gen);
        // -- S4: split-K reduce + GRU gates
        if (gtid < Hc*32){
            int b = gtid & 31, col = gtid >> 5;
            float xr = 0.f, xz = 0.f, xn = 0.f, hr = 0.f, hz = 0.f, hn = 0.f;
#pragma unroll
            for (int z = 0; z < 5; z++){
                size_t ba = (size_t)z*3*Hc*32;
                xr += g_part[ba + (size_t)(col)*32        + b];
                xz += g_part[ba + (size_t)(Hc + col)*32   + b];
                xn += g_part[ba + (size_t)(2*Hc + col)*32 + b];
            }
#pragma unroll
            for (int z = 5; z < 7; z++){
                size_t ba = (size_t)z*3*Hc*32;
                hr += g_part[ba + (size_t)(col)*32        + b];
                hz += g_part[ba + (size_t)(Hc + col)*32   + b];
                hn += g_part[ba + (size_t)(2*Hc + col)*32 + b];
            }
            xr += b_ih[col];        hr += b_hh[col];
            xz += b_ih[Hc + col];   hz += b_hh[Hc + col];
            xn += b_ih[2*Hc + col]; hn += b_hh[2*Hc + col];
            float r = 1.f/(1.f + __expf(-(xr + hr)));
            float z = 1.f/(1.f + __expf(-(xz + hz)));
            float n = tanhf(xn + r*hn);
            float s  = g_xs[b*3584 + 2560 + col];
            float sn = (1.f - z)*n + z*s;
            g_xs[b*3584 + 2560 + col] = sn;
            g_moin[b*3584 + col]      = sn;
        }
        gbar(gen);
        // -- S5: maxout partials (zIdx 0..6, 56 jobs)
        for (int j = blockIdx.x; j < 56; j += gridDim.x){
            int x = j % 8, z = j / 8;
            gemm_tile(smem, 1, s_mo_hi, s_mo_lo, 3584, 8, z*512,
                      g_moin, 3584, z*512, nullptr, nullptr, 0, 2*Mc, z, x*128, 0, 0);
        }
        gbar(gen);
        // -- S6: maxout reduce
        if (gtid < Mc*32){
            int b = gtid & 31, m = gtid >> 5;
            float s0 = 0.f, s1 = 0.f;
#pragma unroll
            for (int z = 0; z < 7; z++){
                size_t ba = (size_t)z*2*Mc*32;
                s0 += g_part[ba + (size_t)(2*m)*32   + b];
                s1 += g_part[ba + (size_t)(2*m+1)*32 + b];
            }
            g_m[b*Mc + m] = fmaxf(s0 + mo_b[2*m], s1 + mo_b[2*m + 1]);
        }
        gbar(gen);
    }
    // -- final fc(63), all blocks
    for (int j = blockIdx.x; j < 250; j += gridDim.x)
        gemm_tile(smem, 0, s_fc_hi, s_fc_lo, 512, 8, 0,
                  g_m, 512, 0, fc_b, logits + (size_t)(Tc-1)*Vc, (long)Tc*Vc,
                  0, 0, j*128, 0, 0);
}

// ---------------- launch --------------------------------------------------------
extern "C" void kernel_launch(void* const* d_in, const int* in_sizes, int n_in,
                              void* d_out, int out_size)
{
    const float* enc_out = (const float*)d_in[0];
    const float* hidden  = (const float*)d_in[1];
    const float* Ws_w    = (const float*)d_in[2];
    const float* Ws_b    = (const float*)d_in[3];
    const float* emb_w   = (const float*)d_in[4];
    const float* emb_b   = (const float*)d_in[5];
    const float* w_ih    = (const float*)d_in[6];
    const float* w_hh    = (const float*)d_in[7];
    const float* b_ih    = (const float*)d_in[8];
    const float* b_hh    = (const float*)d_in[9];
    const float* Wa      = (const float*)d_in[10];
    const float* Ua      = (const float*)d_in[11];
    const float* va      = (const float*)d_in[12];
    const float* mo_w    = (const float*)d_in[13];
    const float* mo_b    = (const float*)d_in[14];
    const float* fc_w    = (const float*)d_in[15];
    const float* fc_b    = (const float*)d_in[16];

    float* logits = (float*)d_out;
    float* alphas = logits + (size_t)Bc*Tc*Vc;

    float *pxs, *pUa;
    __nv_bfloat16 *fc_h, *fc_l, *ih_h, *ih_l, *hh_h, *hh_l, *mo_h, *mo_l,
                  *ua_h, *ua_l, *cat_h, *cat_l, *ws_h, *ws_l;
    cudaGetSymbolAddress((void**)&pxs,   g_xs);
    cudaGetSymbolAddress((void**)&pUa,   g_Ua);
    cudaGetSymbolAddress((void**)&fc_h,  s_fc_hi);  cudaGetSymbolAddress((void**)&fc_l,  s_fc_lo);
    cudaGetSymbolAddress((void**)&ih_h,  s_ih_hi);  cudaGetSymbolAddress((void**)&ih_l,  s_ih_lo);
    cudaGetSymbolAddress((void**)&hh_h,  s_hh_hi);  cudaGetSymbolAddress((void**)&hh_l,  s_hh_lo);
    cudaGetSymbolAddress((void**)&mo_h,  s_mo_hi);  cudaGetSymbolAddress((void**)&mo_l,  s_mo_lo);
    cudaGetSymbolAddress((void**)&ua_h,  s_ua_hi);  cudaGetSymbolAddress((void**)&ua_l,  s_ua_lo);
    cudaGetSymbolAddress((void**)&cat_h, s_cat_hi); cudaGetSymbolAddress((void**)&cat_l, s_cat_lo);
    cudaGetSymbolAddress((void**)&ws_h,  s_ws_hi);  cudaGetSymbolAddress((void**)&ws_l,  s_ws_lo);

    cudaFuncSetAttribute(hm_gemm0, cudaFuncAttributeMaxDynamicSharedMemorySize, SM_DYN);
    cudaFuncSetAttribute(mega,     cudaFuncAttributeMaxDynamicSharedMemorySize, SM_DYN);

    // ---- one-time weight conversion
    conv_hl<<<2048, 256>>>(fc_w,  fc_h,  fc_l,  Vc*Mc);
    conv_hl<<<2048, 256>>>(w_ih,  ih_h,  ih_l,  3*Hc*2560);
    conv_hl<<<1024, 256>>>(w_hh,  hh_h,  hh_l,  3*Hc*Hc);
    conv_hl<<<1024, 256>>>(mo_w,  mo_h,  mo_l,  2*Mc*3584);
    conv_hl<<<1024, 256>>>(Ua,    ua_h,  ua_l,  Hc*2*Hc);
    conv_hl<<<512,  256>>>(Wa,    cat_h, cat_l, Hc*Hc);
    conv_hl<<<512,  256>>>(emb_w, cat_h + (size_t)Hc*Hc, cat_l + (size_t)Hc*Hc, Ec*Hc);
    conv_hl<<<512,  256>>>(Ws_w,  ws_h,  ws_l,  Hc*Hc);

    // ---- si0 = tanh(hidden[1] @ Ws_w^T + Ws_b) -> xs si slot
    hm_gemm0<<<dim3(8,1,1), 256, SM_DYN>>>(ws_h, ws_l, Hc, 16,
        hidden + Bc*Hc, Hc, Ws_b, pxs + 2560, 3584, 1);
    // ---- Ua_enc = enc_out @ Ua^T -> g_Ua[bt][a]
    hm_gemm0<<<dim3(8,64,1), 256, SM_DYN>>>(ua_h, ua_l, 2*Hc, 32,
        enc_out, 2*Hc, nullptr, pUa, Hc, 0);

    // ---- reset barrier state, run all 64 steps in one persistent kernel
    zero_bar<<<1, 1>>>();
    mega<<<NBLK, 256, SM_DYN>>>(enc_out, va, emb_b, b_ih, b_hh, mo_b, fc_b,
                                logits, alphas);
}